// round 8
// baseline (speedup 1.0000x reference)
#include <cuda_runtime.h>
#include <math.h>
#include <stdint.h>

// NoisyTopkRouter — TF32x3 split-fp32 via mma.sync.
// R8: W pre-split to __device__ global (fragment order) by a pre-kernel;
// X split once in producer; fragment-ordered 544B smem slabs so the inner
// loop is 8x LDS.128 (immediate offsets) + 24 HMMA per chunk. 2-stage pipe:
// W via cp.async, X via LDG-register prefetch + STS.
//
// C[32768 x 128] = X[32768 x 2048] * W^T (W rows 0..63 route, 64..127 noise)
// Epilogue: noisy = logits + eps*softplus(noise); top-2; 2-way softmax scatter.

#define MT      128
#define THREADS 512
#define SLAB    544                    // 17 x 32B: bank-rotating slab stride
#define XTILEB  (32 * SLAB)            // 17408 B per hi or lo operand tile
#define STAGEB  (4 * XTILEB)           // Xhi,Xlo,Whi,Wlo = 69632 B
#define SMEMB   (2 * STAGEB)           // 139264 B
#define WKTB    (2 * XTILEB)           // W hi+lo per k-tile = 34816 B
#define WCP     (WKTB / 16)            // 2176 cp16 per W stage
#define NKT     64                     // k-tiles (D=2048 / 32)
#define PADC    130

__device__ unsigned char g_Wpre[NKT * WKTB];   // pre-split W, fragment order

static __device__ __forceinline__ uint32_t f2tf32(float x) {
    uint32_t r;
    asm("cvt.rna.tf32.f32 %0, %1;" : "=r"(r) : "f"(x));
    return r;
}

static __device__ __forceinline__ void mma4(float* d, const uint4 A,
                                            uint32_t b0, uint32_t b1) {
    asm volatile(
        "mma.sync.aligned.m16n8k8.row.col.f32.tf32.tf32.f32 "
        "{%0,%1,%2,%3}, {%4,%5,%6,%7}, {%8,%9}, {%0,%1,%2,%3};"
        : "+f"(d[0]), "+f"(d[1]), "+f"(d[2]), "+f"(d[3])
        : "r"(A.x), "r"(A.y), "r"(A.z), "r"(A.w), "r"(b0), "r"(b1));
}

static __device__ __forceinline__ uint4 lds128(uint32_t a) {
    uint4 v;
    asm volatile("ld.shared.v4.u32 {%0,%1,%2,%3}, [%4];"
                 : "=r"(v.x), "=r"(v.y), "=r"(v.z), "=r"(v.w) : "r"(a));
    return v;
}
static __device__ __forceinline__ void st32(uint32_t a, uint32_t v) {
    asm volatile("st.shared.u32 [%0], %1;" :: "r"(a), "r"(v));
}
static __device__ __forceinline__ void cp16(uint32_t saddr, const void* gaddr) {
    asm volatile("cp.async.ca.shared.global [%0], [%1], 16;"
                 :: "r"(saddr), "l"(gaddr));
}

// ---------------- pre-kernel: split W into fragment-ordered slabs ----------
__global__ void presplit_w(const float* __restrict__ Wr,
                           const float* __restrict__ Wn, int D)
{
    const int kt = blockIdx.x;
    for (int idx = threadIdx.x; idx < 4096; idx += 256) {
        const int n  = idx >> 5;          // 0..127 output col
        const int kc = idx & 31;          // k within tile
        const int k  = kt * 32 + kc;
        const float w = (n < 64) ? Wr[(size_t)n * D + k]
                                 : Wn[(size_t)(n - 64) * D + k];
        const uint32_t hi = f2tf32(w);
        const uint32_t lo = f2tf32(w - __uint_as_float(hi));
        // slab = wn*8 + pair*4 + kcq ; lane = (n&7)*4 + (kc&3)
        // r = glow*2 + k4  (B-frag order: b0/b1 of g=2p, then g=2p+1)
        const int slab = (n >> 5) * 8 + ((n >> 4) & 1) * 4 + (kc >> 3);
        const int ln   = (n & 7) * 4 + (kc & 3);
        const int r    = ((n >> 3) & 1) * 2 + ((kc >> 2) & 1);
        const int off  = slab * SLAB + ln * 16 + r * 4;
        *(uint32_t*)(g_Wpre + (size_t)kt * WKTB + off)          = hi;
        *(uint32_t*)(g_Wpre + (size_t)kt * WKTB + XTILEB + off) = lo;
    }
}

// ---------------- main kernel ---------------------------------------------
__global__ __launch_bounds__(THREADS, 1)
void noisy_topk_router_mma(const float* __restrict__ x,
                           const float* __restrict__ br,
                           const float* __restrict__ bn,
                           const float* __restrict__ eps,
                           float* __restrict__ out,
                           int Ntok, int D, long long out_size)
{
    extern __shared__ char smem[];
    uint32_t smem_u;
    asm("{ .reg .u64 t; cvta.to.shared.u64 t, %1; cvt.u32.u64 %0, t; }"
        : "=r"(smem_u) : "l"(smem));

    const int tid  = threadIdx.x;
    const int wid  = tid >> 5;
    const int lane = tid & 31;
    const int gid  = lane >> 2;
    const int tig  = lane & 3;
    const int wm   = wid & 3;            // 32-token warp row
    const int wn   = wid >> 2;           // 32-col warp col
    const int m0   = blockIdx.x * MT;

    // X producer: thread owns (row pm, k-octet pko): 8 elements per tile
    const int pm  = tid >> 2;            // 0..127
    const int pko = tid & 3;             // 0..3
    const float* xsrc = &x[(size_t)(m0 + pm) * D + pko * 8];
    const uint32_t xslab = (uint32_t)((pm >> 5) * 8 + ((pm >> 4) & 1) * 4 + pko);
    // X r-order = b8 + 2*k4 (A-frag order a0..a3)
    const uint32_t xo = xslab * SLAB + (pm & 7) * 64 + ((pm >> 3) & 1) * 4;

    // consumer bases (within stage): Xhi +0, Xlo +XTILEB, Whi +2*XTILEB, Wlo +3*XTILEB
    const uint32_t cA = smem_u + (wm * 8) * SLAB + lane * 16;
    const uint32_t cB = smem_u + 2 * XTILEB + (wn * 8) * SLAB + lane * 16;

    float acc[2][4][4];
#pragma unroll
    for (int f = 0; f < 2; ++f)
#pragma unroll
        for (int g = 0; g < 4; ++g)
#pragma unroll
            for (int i = 0; i < 4; ++i) acc[f][g][i] = 0.0f;

    const int nTiles = D / 32;           // 64

    // ---- prologue: cp W0,W1 ; LDG+split+STS X0 ----
    for (int i = tid; i < WCP; i += THREADS)
        cp16(smem_u + 2 * XTILEB + i * 16, g_Wpre + i * 16);
    asm volatile("cp.async.commit_group;" ::: "memory");
    for (int i = tid; i < WCP; i += THREADS)
        cp16(smem_u + STAGEB + 2 * XTILEB + i * 16, g_Wpre + WKTB + i * 16);
    asm volatile("cp.async.commit_group;" ::: "memory");

    float4 xv0 = *reinterpret_cast<const float4*>(xsrc);
    float4 xv1 = *reinterpret_cast<const float4*>(xsrc + 4);
    {
        float vals[8] = {xv0.x, xv0.y, xv0.z, xv0.w, xv1.x, xv1.y, xv1.z, xv1.w};
#pragma unroll
        for (int j = 0; j < 8; ++j) {
            const uint32_t hi = f2tf32(vals[j]);
            const uint32_t lo = f2tf32(vals[j] - __uint_as_float(hi));
            const uint32_t ad = smem_u + xo + (j & 3) * 16 + (j >> 2) * 8;
            st32(ad, hi);
            st32(ad + XTILEB, lo);
        }
    }

#pragma unroll 1
    for (int kt = 0; kt < nTiles; ++kt) {
        const int b = kt & 1;
        const uint32_t sb = (uint32_t)(b * STAGEB);

        asm volatile("cp.async.wait_group 1;" ::: "memory");
        __syncthreads();

        // prefetch next X tile into registers (long latency window)
        if (kt + 1 < nTiles) {
            xv0 = *reinterpret_cast<const float4*>(xsrc + (kt + 1) * 32);
            xv1 = *reinterpret_cast<const float4*>(xsrc + (kt + 1) * 32 + 4);
        }

        // ---- compute: 4 chunks x (8 LDS.128 + 24 HMMA) ----
        const uint32_t a  = cA + sb;
        const uint32_t bw = cB + sb;
#pragma unroll
        for (int kcq = 0; kcq < 4; ++kcq) {
            const uint4 Ah0 = lds128(a + kcq * SLAB);
            const uint4 Ah1 = lds128(a + (4 + kcq) * SLAB);
            const uint4 Al0 = lds128(a + XTILEB + kcq * SLAB);
            const uint4 Al1 = lds128(a + XTILEB + (4 + kcq) * SLAB);
            const uint4 Bh0 = lds128(bw + kcq * SLAB);
            const uint4 Bh1 = lds128(bw + (4 + kcq) * SLAB);
            const uint4 Bl0 = lds128(bw + XTILEB + kcq * SLAB);
            const uint4 Bl1 = lds128(bw + XTILEB + (4 + kcq) * SLAB);

            // pass hi*hi
            mma4(acc[0][0], Ah0, Bh0.x, Bh0.y);
            mma4(acc[0][1], Ah0, Bh0.z, Bh0.w);
            mma4(acc[0][2], Ah0, Bh1.x, Bh1.y);
            mma4(acc[0][3], Ah0, Bh1.z, Bh1.w);
            mma4(acc[1][0], Ah1, Bh0.x, Bh0.y);
            mma4(acc[1][1], Ah1, Bh0.z, Bh0.w);
            mma4(acc[1][2], Ah1, Bh1.x, Bh1.y);
            mma4(acc[1][3], Ah1, Bh1.z, Bh1.w);
            // pass hi*lo
            mma4(acc[0][0], Ah0, Bl0.x, Bl0.y);
            mma4(acc[0][1], Ah0, Bl0.z, Bl0.w);
            mma4(acc[0][2], Ah0, Bl1.x, Bl1.y);
            mma4(acc[0][3], Ah0, Bl1.z, Bl1.w);
            mma4(acc[1][0], Ah1, Bl0.x, Bl0.y);
            mma4(acc[1][1], Ah1, Bl0.z, Bl0.w);
            mma4(acc[1][2], Ah1, Bl1.x, Bl1.y);
            mma4(acc[1][3], Ah1, Bl1.z, Bl1.w);
            // pass lo*hi
            mma4(acc[0][0], Al0, Bh0.x, Bh0.y);
            mma4(acc[0][1], Al0, Bh0.z, Bh0.w);
            mma4(acc[0][2], Al0, Bh1.x, Bh1.y);
            mma4(acc[0][3], Al0, Bh1.z, Bh1.w);
            mma4(acc[1][0], Al1, Bh0.x, Bh0.y);
            mma4(acc[1][1], Al1, Bh0.z, Bh0.w);
            mma4(acc[1][2], Al1, Bh1.x, Bh1.y);
            mma4(acc[1][3], Al1, Bh1.z, Bh1.w);
        }
        __syncthreads();   // all reads of stage b done

        // refill: W[kt+2] -> stage b (async), X[kt+1] -> stage b^1
        if (kt + 2 < nTiles) {
            const unsigned char* wsrc = g_Wpre + (size_t)(kt + 2) * WKTB;
            const uint32_t wdst = sb + smem_u + 2 * XTILEB;
            for (int i = tid; i < WCP; i += THREADS)
                cp16(wdst + i * 16, wsrc + i * 16);
        }
        asm volatile("cp.async.commit_group;" ::: "memory");

        if (kt + 1 < nTiles) {
            const uint32_t xb = smem_u + (uint32_t)((b ^ 1) * STAGEB);
            float vals[8] = {xv0.x, xv0.y, xv0.z, xv0.w, xv1.x, xv1.y, xv1.z, xv1.w};
#pragma unroll
            for (int j = 0; j < 8; ++j) {
                const uint32_t hi = f2tf32(vals[j]);
                const uint32_t lo = f2tf32(vals[j] - __uint_as_float(hi));
                const uint32_t ad = xb + xo + (j & 3) * 16 + (j >> 2) * 8;
                st32(ad, hi);
                st32(ad + XTILEB, lo);
            }
        }
    }
    __syncthreads();

    // ---- stage accumulators to smem ----
    float* Cs = reinterpret_cast<float*>(smem);
#pragma unroll
    for (int f = 0; f < 2; ++f)
#pragma unroll
        for (int g = 0; g < 4; ++g) {
            const int row = wm * 32 + f * 16 + gid;
            const int col = wn * 32 + g * 8 + 2 * tig;
            *reinterpret_cast<float2*>(&Cs[row * PADC + col]) =
                make_float2(acc[f][g][0], acc[f][g][1]);
            *reinterpret_cast<float2*>(&Cs[(row + 8) * PADC + col]) =
                make_float2(acc[f][g][2], acc[f][g][3]);
        }
    __syncthreads();

    // ---- epilogue: one thread per token ----
    if (tid < MT) {
        const int tok = m0 + tid;
        const float* crow = &Cs[tid * PADC];

        float v1 = -INFINITY, v2 = -INFINITY;
        int   i1 = -1, i2 = -1;
#pragma unroll 8
        for (int e = 0; e < 64; ++e) {
            const float lg = crow[e]      + __ldg(&br[e]);
            const float ns = crow[64 + e] + __ldg(&bn[e]);
            const float sp = fmaxf(ns, 0.0f) + log1pf(expf(-fabsf(ns)));
            const float nv = lg + __ldg(&eps[(size_t)tok * 64 + e]) * sp;
            if (nv > v1)      { v2 = v1; i2 = i1; v1 = nv; i1 = e; }
            else if (nv > v2) { v2 = nv; i2 = e; }
        }

        const float ed = expf(v2 - v1);
        const float s  = 1.0f + ed;
        const float p1 = 1.0f / s;
        const float p2 = ed / s;

        float* orow = out + (size_t)tok * 64;
#pragma unroll
        for (int e4 = 0; e4 < 64; e4 += 4) {
            float vv[4] = {0.0f, 0.0f, 0.0f, 0.0f};
            if (i1 >= e4 && i1 < e4 + 4) vv[i1 - e4] = p1;
            if (i2 >= e4 && i2 < e4 + 4) vv[i2 - e4] = p2;
            *reinterpret_cast<float4*>(orow + e4) =
                make_float4(vv[0], vv[1], vv[2], vv[3]);
        }

        const long long ibase = (long long)Ntok * 64;
        if (out_size >= ibase + (long long)Ntok * 2) {
            out[ibase + (long long)tok * 2 + 0] = (float)i1;
            out[ibase + (long long)tok * 2 + 1] = (float)i2;
        }
    }
}

extern "C" void kernel_launch(void* const* d_in, const int* in_sizes, int n_in,
                              void* d_out, int out_size)
{
    const float* x   = (const float*)d_in[0];
    const float* Wr  = (const float*)d_in[1];
    const float* br  = (const float*)d_in[2];
    const float* Wn  = (const float*)d_in[3];
    const float* bn  = (const float*)d_in[4];
    const float* eps = (const float*)d_in[5];
    float* out = (float*)d_out;
    (void)n_in;

    const int E    = in_sizes[2];              // 64
    const int D    = in_sizes[1] / E;          // 2048
    const int Ntok = in_sizes[0] / D;          // 32768

    static int configured = 0;                 // idempotent attribute set
    if (!configured) {
        cudaFuncSetAttribute(noisy_topk_router_mma,
                             cudaFuncAttributeMaxDynamicSharedMemorySize, SMEMB);
        configured = 1;
    }

    presplit_w<<<D / 32, 256>>>(Wr, Wn, D);
    noisy_topk_router_mma<<<Ntok / MT, THREADS, SMEMB>>>(
        x, br, bn, eps, out, Ntok, D, (long long)out_size);
}

// round 9
// speedup vs baseline: 1.3740x; 1.3740x over previous
#include <cuda_runtime.h>
#include <math.h>
#include <stdint.h>

// NoisyTopkRouter — TF32x3 split-fp32 via mma.sync.
// R9: W pre-split fragment-ordered in a __device__ global (L2-resident, 2MB),
// consumed by DIRECT LDG.128 (no smem, no cp.async for W). X via cp.async raw
// fp32 (1024 cp16/tile), A-fragments split at consume. Per-tile movement cost
// now fits under the 3072-cycle tensor budget.
//
// C[32768 x 128] = X[32768 x 2048] * W^T (W rows 0..63 route, 64..127 noise)
// Epilogue: noisy = logits + eps*softplus(noise); top-2; 2-way softmax scatter.

#define MT      128
#define THREADS 512
#define NSTAGE  3
#define SROW    36                        // floats per X smem row
#define XSTAGE  (128 * SROW * 4)          // 18432 B
#define SMEMB   (PADC * 128 * 4)          // epilogue Cs dominates: 66560 B
#define PADC    130

#define WSLAB   512                       // W slab stride (bytes), global
#define WTILE   16384                     // hi (or lo) W bytes per k-tile
#define WKTB    (2 * WTILE)               // hi+lo = 32768
#define NKT     64

__device__ unsigned char g_Wpre[NKT * WKTB];   // pre-split W, fragment order

static __device__ __forceinline__ uint32_t f2tf32(float x) {
    uint32_t r;
    asm("cvt.rna.tf32.f32 %0, %1;" : "=r"(r) : "f"(x));
    return r;
}
static __device__ __forceinline__ void split2(float a, uint32_t& hi, uint32_t& lo) {
    hi = f2tf32(a);
    lo = f2tf32(a - __uint_as_float(hi));
}

static __device__ __forceinline__ void mma_tf32(float* d,
                                                uint32_t a0, uint32_t a1,
                                                uint32_t a2, uint32_t a3,
                                                uint32_t b0, uint32_t b1) {
    asm volatile(
        "mma.sync.aligned.m16n8k8.row.col.f32.tf32.tf32.f32 "
        "{%0,%1,%2,%3}, {%4,%5,%6,%7}, {%8,%9}, {%0,%1,%2,%3};"
        : "+f"(d[0]), "+f"(d[1]), "+f"(d[2]), "+f"(d[3])
        : "r"(a0), "r"(a1), "r"(a2), "r"(a3), "r"(b0), "r"(b1));
}

static __device__ __forceinline__ void cp16(uint32_t saddr, const void* gaddr) {
    asm volatile("cp.async.ca.shared.global [%0], [%1], 16;"
                 :: "r"(saddr), "l"(gaddr));
}
static __device__ __forceinline__ uint4 ldg128(const void* p) {
    return __ldg(reinterpret_cast<const uint4*>(p));
}

// ---------------- pre-kernel: split W into fragment-ordered slabs ----------
// 16B unit at (slab, lane): [g0.b0, g0.b1, g1.b0, g1.b1] for MMA lane (gid,tig)
// slab = wn*8 + pair*4 + kcq ; lane = gid*4 + tig
__global__ void presplit_w(const float* __restrict__ Wr,
                           const float* __restrict__ Wn, int D)
{
    const int kt = blockIdx.x;
    for (int idx = threadIdx.x; idx < 4096; idx += 256) {
        const int n  = idx >> 5;          // 0..127 output col
        const int kc = idx & 31;          // k within tile
        const int k  = kt * 32 + kc;
        const float w = (n < 64) ? Wr[(size_t)n * D + k]
                                 : Wn[(size_t)(n - 64) * D + k];
        const uint32_t hi = f2tf32(w);
        const uint32_t lo = f2tf32(w - __uint_as_float(hi));
        const int slab = (n >> 5) * 8 + ((n >> 4) & 1) * 4 + (kc >> 3);
        const int ln   = (n & 7) * 4 + (kc & 3);
        const int r    = ((n >> 3) & 1) * 2 + ((kc >> 2) & 1);
        const int off  = slab * WSLAB + ln * 16 + r * 4;
        *(uint32_t*)(g_Wpre + (size_t)kt * WKTB + off)         = hi;
        *(uint32_t*)(g_Wpre + (size_t)kt * WKTB + WTILE + off) = lo;
    }
}

// ---------------- main kernel ---------------------------------------------
__global__ __launch_bounds__(THREADS, 1)
void noisy_topk_router_mma(const float* __restrict__ x,
                           const float* __restrict__ br,
                           const float* __restrict__ bn,
                           const float* __restrict__ eps,
                           float* __restrict__ out,
                           int Ntok, int D, long long out_size)
{
    extern __shared__ char smem[];
    uint32_t smem_u;
    asm("{ .reg .u64 t; cvta.to.shared.u64 t, %1; cvt.u32.u64 %0, t; }"
        : "=r"(smem_u) : "l"(smem));

    const int tid  = threadIdx.x;
    const int wid  = tid >> 5;      // 0..15
    const int lane = tid & 31;
    const int gid  = lane >> 2;
    const int tig  = lane & 3;
    const int wm   = wid & 3;       // warp m-row (32 tokens)
    const int wn   = wid >> 2;      // warp n-col (32 outputs)
    const int m0   = blockIdx.x * MT;

    // X producer: 2 cp16 per thread per stage
    // prow = tid>>2 (0..127), pqf = (tid&3)*4 -> floats pqf+{0..3} and pqf+{16..19}
    const int prow = tid >> 2;
    const int pqf  = (tid & 3) * 4;
    const float* xsrc = &x[(size_t)(m0 + prow) * D + pqf];
    const uint32_t pdst = smem_u + prow * (SROW * 4) + pqf * 4;

    // W fragment base for this warp (direct global)
    const unsigned char* wbase = g_Wpre + (size_t)(wn * 8) * WSLAB + lane * 16;

    float acc[2][4][4];
#pragma unroll
    for (int f = 0; f < 2; ++f)
#pragma unroll
        for (int g = 0; g < 4; ++g)
#pragma unroll
            for (int i = 0; i < 4; ++i) acc[f][g][i] = 0.0f;

    const int nTiles = D / 32;      // 64

    // ---- prologue: X stages 0,1 in flight ----
#pragma unroll
    for (int s = 0; s < 2; ++s) {
        cp16(pdst + s * XSTAGE, xsrc + s * 32);
        cp16(pdst + s * XSTAGE + 64, xsrc + s * 32 + 16);
        asm volatile("cp.async.commit_group;" ::: "memory");
    }

    int stage = 0;
#pragma unroll 1
    for (int kt = 0; kt < nTiles; ++kt) {
        if (kt + 2 < nTiles) {
            const int s2 = (stage + 2 >= NSTAGE) ? stage + 2 - NSTAGE : stage + 2;
            cp16(pdst + s2 * XSTAGE, xsrc + (kt + 2) * 32);
            cp16(pdst + s2 * XSTAGE + 64, xsrc + (kt + 2) * 32 + 16);
        }
        asm volatile("cp.async.commit_group;" ::: "memory");
        asm volatile("cp.async.wait_group 2;" ::: "memory");
        __syncthreads();

        const float* Xs = reinterpret_cast<const float*>(smem + stage * XSTAGE);
        const float* aB = Xs + (wm * 32 + gid) * SROW + tig;
        const unsigned char* wkt = wbase + (size_t)kt * WKTB;

#pragma unroll
        for (int kcq = 0; kcq < 4; ++kcq) {
            // B fragments: 4 coalesced LDG.128 from pre-split W (L1/L2 hit)
            const unsigned char* p = wkt + kcq * WSLAB;
            const uint4 Bh0 = ldg128(p);
            const uint4 Bh1 = ldg128(p + 4 * WSLAB);
            const uint4 Bl0 = ldg128(p + WTILE);
            const uint4 Bl1 = ldg128(p + WTILE + 4 * WSLAB);

            // A fragments: 8 LDS.32 + split at consume
            uint32_t Ah[2][4], Al[2][4];
#pragma unroll
            for (int f = 0; f < 2; ++f) {
                const float* q = aB + f * 16 * SROW + kcq * 8;
                split2(q[0],            Ah[f][0], Al[f][0]);
                split2(q[8 * SROW],     Ah[f][1], Al[f][1]);
                split2(q[4],            Ah[f][2], Al[f][2]);
                split2(q[8 * SROW + 4], Ah[f][3], Al[f][3]);
            }

            // pass hi*hi
#pragma unroll
            for (int f = 0; f < 2; ++f) {
                mma_tf32(acc[f][0], Ah[f][0], Ah[f][1], Ah[f][2], Ah[f][3], Bh0.x, Bh0.y);
                mma_tf32(acc[f][1], Ah[f][0], Ah[f][1], Ah[f][2], Ah[f][3], Bh0.z, Bh0.w);
                mma_tf32(acc[f][2], Ah[f][0], Ah[f][1], Ah[f][2], Ah[f][3], Bh1.x, Bh1.y);
                mma_tf32(acc[f][3], Ah[f][0], Ah[f][1], Ah[f][2], Ah[f][3], Bh1.z, Bh1.w);
            }
            // pass hi*lo
#pragma unroll
            for (int f = 0; f < 2; ++f) {
                mma_tf32(acc[f][0], Ah[f][0], Ah[f][1], Ah[f][2], Ah[f][3], Bl0.x, Bl0.y);
                mma_tf32(acc[f][1], Ah[f][0], Ah[f][1], Ah[f][2], Ah[f][3], Bl0.z, Bl0.w);
                mma_tf32(acc[f][2], Ah[f][0], Ah[f][1], Ah[f][2], Ah[f][3], Bl1.x, Bl1.y);
                mma_tf32(acc[f][3], Ah[f][0], Ah[f][1], Ah[f][2], Ah[f][3], Bl1.z, Bl1.w);
            }
            // pass lo*hi
#pragma unroll
            for (int f = 0; f < 2; ++f) {
                mma_tf32(acc[f][0], Al[f][0], Al[f][1], Al[f][2], Al[f][3], Bh0.x, Bh0.y);
                mma_tf32(acc[f][1], Al[f][0], Al[f][1], Al[f][2], Al[f][3], Bh0.z, Bh0.w);
                mma_tf32(acc[f][2], Al[f][0], Al[f][1], Al[f][2], Al[f][3], Bh1.x, Bh1.y);
                mma_tf32(acc[f][3], Al[f][0], Al[f][1], Al[f][2], Al[f][3], Bh1.z, Bh1.w);
            }
        }
        __syncthreads();
        stage = (stage + 1 == NSTAGE) ? 0 : stage + 1;
    }

    // ---- stage accumulators to smem ----
    float* Cs = reinterpret_cast<float*>(smem);
#pragma unroll
    for (int f = 0; f < 2; ++f)
#pragma unroll
        for (int g = 0; g < 4; ++g) {
            const int row = wm * 32 + f * 16 + gid;
            const int col = wn * 32 + g * 8 + 2 * tig;
            *reinterpret_cast<float2*>(&Cs[row * PADC + col]) =
                make_float2(acc[f][g][0], acc[f][g][1]);
            *reinterpret_cast<float2*>(&Cs[(row + 8) * PADC + col]) =
                make_float2(acc[f][g][2], acc[f][g][3]);
        }
    __syncthreads();

    // ---- epilogue: one thread per token ----
    if (tid < MT) {
        const int tok = m0 + tid;
        const float* crow = &Cs[tid * PADC];

        float v1 = -INFINITY, v2 = -INFINITY;
        int   i1 = -1, i2 = -1;
#pragma unroll 8
        for (int e = 0; e < 64; ++e) {
            const float lg = crow[e]      + __ldg(&br[e]);
            const float ns = crow[64 + e] + __ldg(&bn[e]);
            const float sp = fmaxf(ns, 0.0f) + log1pf(expf(-fabsf(ns)));
            const float nv = lg + __ldg(&eps[(size_t)tok * 64 + e]) * sp;
            if (nv > v1)      { v2 = v1; i2 = i1; v1 = nv; i1 = e; }
            else if (nv > v2) { v2 = nv; i2 = e; }
        }

        const float ed = expf(v2 - v1);
        const float s  = 1.0f + ed;
        const float p1 = 1.0f / s;
        const float p2 = ed / s;

        float* orow = out + (size_t)tok * 64;
#pragma unroll
        for (int e4 = 0; e4 < 64; e4 += 4) {
            float vv[4] = {0.0f, 0.0f, 0.0f, 0.0f};
            if (i1 >= e4 && i1 < e4 + 4) vv[i1 - e4] = p1;
            if (i2 >= e4 && i2 < e4 + 4) vv[i2 - e4] = p2;
            *reinterpret_cast<float4*>(orow + e4) =
                make_float4(vv[0], vv[1], vv[2], vv[3]);
        }

        const long long ibase = (long long)Ntok * 64;
        if (out_size >= ibase + (long long)Ntok * 2) {
            out[ibase + (long long)tok * 2 + 0] = (float)i1;
            out[ibase + (long long)tok * 2 + 1] = (float)i2;
        }
    }
}

extern "C" void kernel_launch(void* const* d_in, const int* in_sizes, int n_in,
                              void* d_out, int out_size)
{
    const float* x   = (const float*)d_in[0];
    const float* Wr  = (const float*)d_in[1];
    const float* br  = (const float*)d_in[2];
    const float* Wn  = (const float*)d_in[3];
    const float* bn  = (const float*)d_in[4];
    const float* eps = (const float*)d_in[5];
    float* out = (float*)d_out;
    (void)n_in;

    const int E    = in_sizes[2];              // 64
    const int D    = in_sizes[1] / E;          // 2048
    const int Ntok = in_sizes[0] / D;          // 32768

    static int configured = 0;                 // idempotent attribute set
    if (!configured) {
        cudaFuncSetAttribute(noisy_topk_router_mma,
                             cudaFuncAttributeMaxDynamicSharedMemorySize, SMEMB);
        configured = 1;
    }

    presplit_w<<<D / 32, 256>>>(Wr, Wn, D);
    noisy_topk_router_mma<<<Ntok / MT, THREADS, SMEMB>>>(
        x, br, bn, eps, out, Ntok, D, (long long)out_size);
}

// round 10
// speedup vs baseline: 1.5383x; 1.1196x over previous
#include <cuda_runtime.h>
#include <math.h>
#include <stdint.h>

// NoisyTopkRouter — TF32x3 split-fp32 via mma.sync.
// R10 = R9 with W moved from per-chunk direct LDG (L2-latency-exposed) into a
// cp.async 3-stage smem ring (fragment-ordered 512B slabs -> conflict-free
// LDS.128 B-fragments). X path unchanged (cp.async raw fp32, split at consume).
//
// C[32768 x 128] = X[32768 x 2048] * W^T (W rows 0..63 route, 64..127 noise)
// Epilogue: noisy = logits + eps*softplus(noise); top-2; 2-way softmax scatter.

#define MT      128
#define THREADS 512
#define NSTAGE  3
#define SROW    36                        // floats per X smem row
#define XSTAGE  (128 * SROW * 4)          // 18432 B
#define WSLAB   512                       // W slab stride (bytes)
#define WTILE   16384                     // hi (or lo) W bytes per k-tile
#define WKTB    (2 * WTILE)               // hi+lo = 32768
#define WBASE   (NSTAGE * XSTAGE)         // W ring starts after X ring
#define SMEMB   (WBASE + NSTAGE * WKTB)   // 55296 + 98304 = 153600 B
#define NKT     64
#define PADC    130

__device__ unsigned char g_Wpre[NKT * WKTB];   // pre-split W, fragment order

static __device__ __forceinline__ uint32_t f2tf32(float x) {
    uint32_t r;
    asm("cvt.rna.tf32.f32 %0, %1;" : "=r"(r) : "f"(x));
    return r;
}
static __device__ __forceinline__ void split2(float a, uint32_t& hi, uint32_t& lo) {
    hi = f2tf32(a);
    lo = f2tf32(a - __uint_as_float(hi));
}

static __device__ __forceinline__ void mma_tf32(float* d,
                                                uint32_t a0, uint32_t a1,
                                                uint32_t a2, uint32_t a3,
                                                uint32_t b0, uint32_t b1) {
    asm volatile(
        "mma.sync.aligned.m16n8k8.row.col.f32.tf32.tf32.f32 "
        "{%0,%1,%2,%3}, {%4,%5,%6,%7}, {%8,%9}, {%0,%1,%2,%3};"
        : "+f"(d[0]), "+f"(d[1]), "+f"(d[2]), "+f"(d[3])
        : "r"(a0), "r"(a1), "r"(a2), "r"(a3), "r"(b0), "r"(b1));
}

static __device__ __forceinline__ void cp16(uint32_t saddr, const void* gaddr) {
    asm volatile("cp.async.ca.shared.global [%0], [%1], 16;"
                 :: "r"(saddr), "l"(gaddr));
}
static __device__ __forceinline__ uint4 lds128(uint32_t a) {
    uint4 v;
    asm volatile("ld.shared.v4.u32 {%0,%1,%2,%3}, [%4];"
                 : "=r"(v.x), "=r"(v.y), "=r"(v.z), "=r"(v.w) : "r"(a));
    return v;
}

// ---------------- pre-kernel: split W into fragment-ordered slabs ----------
// 16B unit at (slab, lane): [g0.b0, g0.b1, g1.b0, g1.b1] for MMA lane (gid,tig)
// slab = wn*8 + pair*4 + kcq ; lane = gid*4 + tig
__global__ void presplit_w(const float* __restrict__ Wr,
                           const float* __restrict__ Wn, int D)
{
    const int kt = blockIdx.x;
    for (int idx = threadIdx.x; idx < 4096; idx += 256) {
        const int n  = idx >> 5;          // 0..127 output col
        const int kc = idx & 31;          // k within tile
        const int k  = kt * 32 + kc;
        const float w = (n < 64) ? Wr[(size_t)n * D + k]
                                 : Wn[(size_t)(n - 64) * D + k];
        const uint32_t hi = f2tf32(w);
        const uint32_t lo = f2tf32(w - __uint_as_float(hi));
        const int slab = (n >> 5) * 8 + ((n >> 4) & 1) * 4 + (kc >> 3);
        const int ln   = (n & 7) * 4 + (kc & 3);
        const int r    = ((n >> 3) & 1) * 2 + ((kc >> 2) & 1);
        const int off  = slab * WSLAB + ln * 16 + r * 4;
        *(uint32_t*)(g_Wpre + (size_t)kt * WKTB + off)         = hi;
        *(uint32_t*)(g_Wpre + (size_t)kt * WKTB + WTILE + off) = lo;
    }
}

// ---------------- main kernel ---------------------------------------------
__global__ __launch_bounds__(THREADS, 1)
void noisy_topk_router_mma(const float* __restrict__ x,
                           const float* __restrict__ br,
                           const float* __restrict__ bn,
                           const float* __restrict__ eps,
                           float* __restrict__ out,
                           int Ntok, int D, long long out_size)
{
    extern __shared__ char smem[];
    uint32_t smem_u;
    asm("{ .reg .u64 t; cvta.to.shared.u64 t, %1; cvt.u32.u64 %0, t; }"
        : "=r"(smem_u) : "l"(smem));

    const int tid  = threadIdx.x;
    const int wid  = tid >> 5;      // 0..15
    const int lane = tid & 31;
    const int gid  = lane >> 2;
    const int tig  = lane & 3;
    const int wm   = wid & 3;       // warp m-row (32 tokens)
    const int wn   = wid >> 2;      // warp n-col (32 outputs)
    const int m0   = blockIdx.x * MT;

    // X producer: 2 cp16/thread/stage (prow = tid>>2, pqf = (tid&3)*4)
    const int prow = tid >> 2;
    const int pqf  = (tid & 3) * 4;
    const float* xsrc = &x[(size_t)(m0 + prow) * D + pqf];
    const uint32_t pdst = smem_u + prow * (SROW * 4) + pqf * 4;

    // W producer: 4 cp16/thread/stage, linear copy (layout preserved)
    const uint32_t wdst0 = smem_u + WBASE + tid * 16;

    // W consumer fragment base (within a W stage)
    const uint32_t wfb = smem_u + WBASE + (uint32_t)(wn * 8) * WSLAB + lane * 16;

    float acc[2][4][4];
#pragma unroll
    for (int f = 0; f < 2; ++f)
#pragma unroll
        for (int g = 0; g < 4; ++g)
#pragma unroll
            for (int i = 0; i < 4; ++i) acc[f][g][i] = 0.0f;

    const int nTiles = D / 32;      // 64

    // ---- prologue: stages 0,1 (X and W) in flight ----
#pragma unroll
    for (int s = 0; s < 2; ++s) {
        cp16(pdst + s * XSTAGE, xsrc + s * 32);
        cp16(pdst + s * XSTAGE + 64, xsrc + s * 32 + 16);
        const unsigned char* wsrc = g_Wpre + (size_t)s * WKTB;
#pragma unroll
        for (int q = 0; q < 4; ++q)
            cp16(wdst0 + s * WKTB + q * 8192, wsrc + tid * 16 + q * 8192);
        asm volatile("cp.async.commit_group;" ::: "memory");
    }

    int stage = 0;
#pragma unroll 1
    for (int kt = 0; kt < nTiles; ++kt) {
        if (kt + 2 < nTiles) {
            const int s2 = (stage + 2 >= NSTAGE) ? stage + 2 - NSTAGE : stage + 2;
            cp16(pdst + s2 * XSTAGE, xsrc + (kt + 2) * 32);
            cp16(pdst + s2 * XSTAGE + 64, xsrc + (kt + 2) * 32 + 16);
            const unsigned char* wsrc = g_Wpre + (size_t)(kt + 2) * WKTB;
#pragma unroll
            for (int q = 0; q < 4; ++q)
                cp16(wdst0 + s2 * WKTB + q * 8192, wsrc + tid * 16 + q * 8192);
        }
        asm volatile("cp.async.commit_group;" ::: "memory");
        asm volatile("cp.async.wait_group 2;" ::: "memory");
        __syncthreads();

        const float* Xs = reinterpret_cast<const float*>(smem + stage * XSTAGE);
        const float* aB = Xs + (wm * 32 + gid) * SROW + tig;
        const uint32_t wst = wfb + (uint32_t)(stage * WKTB);

#pragma unroll
        for (int kcq = 0; kcq < 4; ++kcq) {
            // B fragments: 4 conflict-free LDS.128 from fragment-ordered W
            const uint4 Bh0 = lds128(wst + kcq * WSLAB);
            const uint4 Bh1 = lds128(wst + (4 + kcq) * WSLAB);
            const uint4 Bl0 = lds128(wst + WTILE + kcq * WSLAB);
            const uint4 Bl1 = lds128(wst + WTILE + (4 + kcq) * WSLAB);

            // A fragments: 8 LDS.32 + split at consume
            uint32_t Ah[2][4], Al[2][4];
#pragma unroll
            for (int f = 0; f < 2; ++f) {
                const float* q = aB + f * 16 * SROW + kcq * 8;
                split2(q[0],            Ah[f][0], Al[f][0]);
                split2(q[8 * SROW],     Ah[f][1], Al[f][1]);
                split2(q[4],            Ah[f][2], Al[f][2]);
                split2(q[8 * SROW + 4], Ah[f][3], Al[f][3]);
            }

            // pass hi*hi
#pragma unroll
            for (int f = 0; f < 2; ++f) {
                mma_tf32(acc[f][0], Ah[f][0], Ah[f][1], Ah[f][2], Ah[f][3], Bh0.x, Bh0.y);
                mma_tf32(acc[f][1], Ah[f][0], Ah[f][1], Ah[f][2], Ah[f][3], Bh0.z, Bh0.w);
                mma_tf32(acc[f][2], Ah[f][0], Ah[f][1], Ah[f][2], Ah[f][3], Bh1.x, Bh1.y);
                mma_tf32(acc[f][3], Ah[f][0], Ah[f][1], Ah[f][2], Ah[f][3], Bh1.z, Bh1.w);
            }
            // pass hi*lo
#pragma unroll
            for (int f = 0; f < 2; ++f) {
                mma_tf32(acc[f][0], Ah[f][0], Ah[f][1], Ah[f][2], Ah[f][3], Bl0.x, Bl0.y);
                mma_tf32(acc[f][1], Ah[f][0], Ah[f][1], Ah[f][2], Ah[f][3], Bl0.z, Bl0.w);
                mma_tf32(acc[f][2], Ah[f][0], Ah[f][1], Ah[f][2], Ah[f][3], Bl1.x, Bl1.y);
                mma_tf32(acc[f][3], Ah[f][0], Ah[f][1], Ah[f][2], Ah[f][3], Bl1.z, Bl1.w);
            }
            // pass lo*hi
#pragma unroll
            for (int f = 0; f < 2; ++f) {
                mma_tf32(acc[f][0], Al[f][0], Al[f][1], Al[f][2], Al[f][3], Bh0.x, Bh0.y);
                mma_tf32(acc[f][1], Al[f][0], Al[f][1], Al[f][2], Al[f][3], Bh0.z, Bh0.w);
                mma_tf32(acc[f][2], Al[f][0], Al[f][1], Al[f][2], Al[f][3], Bh1.x, Bh1.y);
                mma_tf32(acc[f][3], Al[f][0], Al[f][1], Al[f][2], Al[f][3], Bh1.z, Bh1.w);
            }
        }
        __syncthreads();
        stage = (stage + 1 == NSTAGE) ? 0 : stage + 1;
    }

    // ---- stage accumulators to smem ----
    float* Cs = reinterpret_cast<float*>(smem);
#pragma unroll
    for (int f = 0; f < 2; ++f)
#pragma unroll
        for (int g = 0; g < 4; ++g) {
            const int row = wm * 32 + f * 16 + gid;
            const int col = wn * 32 + g * 8 + 2 * tig;
            *reinterpret_cast<float2*>(&Cs[row * PADC + col]) =
                make_float2(acc[f][g][0], acc[f][g][1]);
            *reinterpret_cast<float2*>(&Cs[(row + 8) * PADC + col]) =
                make_float2(acc[f][g][2], acc[f][g][3]);
        }
    __syncthreads();

    // ---- epilogue: one thread per token ----
    if (tid < MT) {
        const int tok = m0 + tid;
        const float* crow = &Cs[tid * PADC];

        float v1 = -INFINITY, v2 = -INFINITY;
        int   i1 = -1, i2 = -1;
#pragma unroll 8
        for (int e = 0; e < 64; ++e) {
            const float lg = crow[e]      + __ldg(&br[e]);
            const float ns = crow[64 + e] + __ldg(&bn[e]);
            const float sp = fmaxf(ns, 0.0f) + log1pf(expf(-fabsf(ns)));
            const float nv = lg + __ldg(&eps[(size_t)tok * 64 + e]) * sp;
            if (nv > v1)      { v2 = v1; i2 = i1; v1 = nv; i1 = e; }
            else if (nv > v2) { v2 = nv; i2 = e; }
        }

        const float ed = expf(v2 - v1);
        const float s  = 1.0f + ed;
        const float p1 = 1.0f / s;
        const float p2 = ed / s;

        float* orow = out + (size_t)tok * 64;
#pragma unroll
        for (int e4 = 0; e4 < 64; e4 += 4) {
            float vv[4] = {0.0f, 0.0f, 0.0f, 0.0f};
            if (i1 >= e4 && i1 < e4 + 4) vv[i1 - e4] = p1;
            if (i2 >= e4 && i2 < e4 + 4) vv[i2 - e4] = p2;
            *reinterpret_cast<float4*>(orow + e4) =
                make_float4(vv[0], vv[1], vv[2], vv[3]);
        }

        const long long ibase = (long long)Ntok * 64;
        if (out_size >= ibase + (long long)Ntok * 2) {
            out[ibase + (long long)tok * 2 + 0] = (float)i1;
            out[ibase + (long long)tok * 2 + 1] = (float)i2;
        }
    }
}

extern "C" void kernel_launch(void* const* d_in, const int* in_sizes, int n_in,
                              void* d_out, int out_size)
{
    const float* x   = (const float*)d_in[0];
    const float* Wr  = (const float*)d_in[1];
    const float* br  = (const float*)d_in[2];
    const float* Wn  = (const float*)d_in[3];
    const float* bn  = (const float*)d_in[4];
    const float* eps = (const float*)d_in[5];
    float* out = (float*)d_out;
    (void)n_in;

    const int E    = in_sizes[2];              // 64
    const int D    = in_sizes[1] / E;          // 2048
    const int Ntok = in_sizes[0] / D;          // 32768

    static int configured = 0;                 // idempotent attribute set
    if (!configured) {
        cudaFuncSetAttribute(noisy_topk_router_mma,
                             cudaFuncAttributeMaxDynamicSharedMemorySize, SMEMB);
        configured = 1;
    }

    presplit_w<<<D / 32, 256>>>(Wr, Wn, D);
    noisy_topk_router_mma<<<Ntok / MT, THREADS, SMEMB>>>(
        x, br, bn, eps, out, Ntok, D, (long long)out_size);
}

// round 11
// speedup vs baseline: 1.5429x; 1.0030x over previous
#include <cuda_runtime.h>
#include <math.h>
#include <stdint.h>

// NoisyTopkRouter — TF32x3 split-fp32 via mma.sync.
// R11 = R10 + cross-chunk fragment double-buffering: the 12 LDS of chunk
// kcq+1 issue before the 24 MMAs of chunk kcq, hiding LDS latency and the
// X split ALU chain behind MMA issue.
//
// C[32768 x 128] = X[32768 x 2048] * W^T (W rows 0..63 route, 64..127 noise)
// Epilogue: noisy = logits + eps*softplus(noise); top-2; 2-way softmax scatter.

#define MT      128
#define THREADS 512
#define NSTAGE  3
#define SROW    36                        // floats per X smem row
#define XSTAGE  (128 * SROW * 4)          // 18432 B
#define WSLAB   512                       // W slab stride (bytes)
#define WTILE   16384                     // hi (or lo) W bytes per k-tile
#define WKTB    (2 * WTILE)               // hi+lo = 32768
#define WBASE   (NSTAGE * XSTAGE)         // W ring starts after X ring
#define SMEMB   (WBASE + NSTAGE * WKTB)   // 153600 B
#define NKT     64
#define PADC    130

__device__ unsigned char g_Wpre[NKT * WKTB];   // pre-split W, fragment order

static __device__ __forceinline__ uint32_t f2tf32(float x) {
    uint32_t r;
    asm("cvt.rna.tf32.f32 %0, %1;" : "=r"(r) : "f"(x));
    return r;
}
static __device__ __forceinline__ void split2(float a, uint32_t& hi, uint32_t& lo) {
    hi = f2tf32(a);
    lo = f2tf32(a - __uint_as_float(hi));
}

static __device__ __forceinline__ void mma_tf32(float* d,
                                                uint32_t a0, uint32_t a1,
                                                uint32_t a2, uint32_t a3,
                                                uint32_t b0, uint32_t b1) {
    asm volatile(
        "mma.sync.aligned.m16n8k8.row.col.f32.tf32.tf32.f32 "
        "{%0,%1,%2,%3}, {%4,%5,%6,%7}, {%8,%9}, {%0,%1,%2,%3};"
        : "+f"(d[0]), "+f"(d[1]), "+f"(d[2]), "+f"(d[3])
        : "r"(a0), "r"(a1), "r"(a2), "r"(a3), "r"(b0), "r"(b1));
}

static __device__ __forceinline__ void cp16(uint32_t saddr, const void* gaddr) {
    asm volatile("cp.async.ca.shared.global [%0], [%1], 16;"
                 :: "r"(saddr), "l"(gaddr));
}
static __device__ __forceinline__ uint4 lds128(uint32_t a) {
    uint4 v;
    asm volatile("ld.shared.v4.u32 {%0,%1,%2,%3}, [%4];"
                 : "=r"(v.x), "=r"(v.y), "=r"(v.z), "=r"(v.w) : "r"(a));
    return v;
}

// ---------------- pre-kernel: split W into fragment-ordered slabs ----------
__global__ void presplit_w(const float* __restrict__ Wr,
                           const float* __restrict__ Wn, int D)
{
    const int kt = blockIdx.x;
    for (int idx = threadIdx.x; idx < 4096; idx += 256) {
        const int n  = idx >> 5;
        const int kc = idx & 31;
        const int k  = kt * 32 + kc;
        const float w = (n < 64) ? Wr[(size_t)n * D + k]
                                 : Wn[(size_t)(n - 64) * D + k];
        const uint32_t hi = f2tf32(w);
        const uint32_t lo = f2tf32(w - __uint_as_float(hi));
        const int slab = (n >> 5) * 8 + ((n >> 4) & 1) * 4 + (kc >> 3);
        const int ln   = (n & 7) * 4 + (kc & 3);
        const int r    = ((n >> 3) & 1) * 2 + ((kc >> 2) & 1);
        const int off  = slab * WSLAB + ln * 16 + r * 4;
        *(uint32_t*)(g_Wpre + (size_t)kt * WKTB + off)         = hi;
        *(uint32_t*)(g_Wpre + (size_t)kt * WKTB + WTILE + off) = lo;
    }
}

// ---------------- main kernel ---------------------------------------------
__global__ __launch_bounds__(THREADS, 1)
void noisy_topk_router_mma(const float* __restrict__ x,
                           const float* __restrict__ br,
                           const float* __restrict__ bn,
                           const float* __restrict__ eps,
                           float* __restrict__ out,
                           int Ntok, int D, long long out_size)
{
    extern __shared__ char smem[];
    uint32_t smem_u;
    asm("{ .reg .u64 t; cvta.to.shared.u64 t, %1; cvt.u32.u64 %0, t; }"
        : "=r"(smem_u) : "l"(smem));

    const int tid  = threadIdx.x;
    const int wid  = tid >> 5;
    const int lane = tid & 31;
    const int gid  = lane >> 2;
    const int tig  = lane & 3;
    const int wm   = wid & 3;
    const int wn   = wid >> 2;
    const int m0   = blockIdx.x * MT;

    // X producer: 2 cp16/thread/stage
    const int prow = tid >> 2;
    const int pqf  = (tid & 3) * 4;
    const float* xsrc = &x[(size_t)(m0 + prow) * D + pqf];
    const uint32_t pdst = smem_u + prow * (SROW * 4) + pqf * 4;

    // W producer: 4 cp16/thread/stage (linear, layout preserved)
    const uint32_t wdst0 = smem_u + WBASE + tid * 16;

    // W consumer fragment base (within a W stage)
    const uint32_t wfb = smem_u + WBASE + (uint32_t)(wn * 8) * WSLAB + lane * 16;

    float acc[2][4][4];
#pragma unroll
    for (int f = 0; f < 2; ++f)
#pragma unroll
        for (int g = 0; g < 4; ++g)
#pragma unroll
            for (int i = 0; i < 4; ++i) acc[f][g][i] = 0.0f;

    const int nTiles = D / 32;      // 64

    // ---- prologue: stages 0,1 (X and W) in flight ----
#pragma unroll
    for (int s = 0; s < 2; ++s) {
        cp16(pdst + s * XSTAGE, xsrc + s * 32);
        cp16(pdst + s * XSTAGE + 64, xsrc + s * 32 + 16);
        const unsigned char* wsrc = g_Wpre + (size_t)s * WKTB;
#pragma unroll
        for (int q = 0; q < 4; ++q)
            cp16(wdst0 + s * WKTB + q * 8192, wsrc + tid * 16 + q * 8192);
        asm volatile("cp.async.commit_group;" ::: "memory");
    }

    int stage = 0;
#pragma unroll 1
    for (int kt = 0; kt < nTiles; ++kt) {
        if (kt + 2 < nTiles) {
            const int s2 = (stage + 2 >= NSTAGE) ? stage + 2 - NSTAGE : stage + 2;
            cp16(pdst + s2 * XSTAGE, xsrc + (kt + 2) * 32);
            cp16(pdst + s2 * XSTAGE + 64, xsrc + (kt + 2) * 32 + 16);
            const unsigned char* wsrc = g_Wpre + (size_t)(kt + 2) * WKTB;
#pragma unroll
            for (int q = 0; q < 4; ++q)
                cp16(wdst0 + s2 * WKTB + q * 8192, wsrc + tid * 16 + q * 8192);
        }
        asm volatile("cp.async.commit_group;" ::: "memory");
        asm volatile("cp.async.wait_group 2;" ::: "memory");
        __syncthreads();

        const float* Xs = reinterpret_cast<const float*>(smem + stage * XSTAGE);
        const float* aB = Xs + (wm * 32 + gid) * SROW + tig;
        const uint32_t wst = wfb + (uint32_t)(stage * WKTB);

        // ---- cross-chunk fragment double-buffer pipeline ----
        uint4  Wf[2][4];               // [buf][Bh0,Bh1,Bl0,Bl1]
        float  Xf[2][8];               // [buf][raw A-frag floats]

        // load chunk 0 fragments into buf 0
        Wf[0][0] = lds128(wst);
        Wf[0][1] = lds128(wst + 4 * WSLAB);
        Wf[0][2] = lds128(wst + WTILE);
        Wf[0][3] = lds128(wst + WTILE + 4 * WSLAB);
        {
            const float* q0 = aB;
            const float* q1 = aB + 16 * SROW;
            Xf[0][0] = q0[0]; Xf[0][1] = q0[8 * SROW];
            Xf[0][2] = q0[4]; Xf[0][3] = q0[8 * SROW + 4];
            Xf[0][4] = q1[0]; Xf[0][5] = q1[8 * SROW];
            Xf[0][6] = q1[4]; Xf[0][7] = q1[8 * SROW + 4];
        }

#pragma unroll
        for (int kcq = 0; kcq < 4; ++kcq) {
            const int cur = kcq & 1;
            const int nxt = cur ^ 1;

            // issue next chunk's loads first (latency hidden behind MMAs)
            if (kcq < 3) {
                const uint32_t wo = wst + (kcq + 1) * WSLAB;
                Wf[nxt][0] = lds128(wo);
                Wf[nxt][1] = lds128(wo + 4 * WSLAB);
                Wf[nxt][2] = lds128(wo + WTILE);
                Wf[nxt][3] = lds128(wo + WTILE + 4 * WSLAB);
                const float* q0 = aB + (kcq + 1) * 8;
                const float* q1 = q0 + 16 * SROW;
                Xf[nxt][0] = q0[0]; Xf[nxt][1] = q0[8 * SROW];
                Xf[nxt][2] = q0[4]; Xf[nxt][3] = q0[8 * SROW + 4];
                Xf[nxt][4] = q1[0]; Xf[nxt][5] = q1[8 * SROW];
                Xf[nxt][6] = q1[4]; Xf[nxt][7] = q1[8 * SROW + 4];
            }

            // split current X fragments
            uint32_t Ah[2][4], Al[2][4];
#pragma unroll
            for (int f = 0; f < 2; ++f)
#pragma unroll
                for (int i = 0; i < 4; ++i)
                    split2(Xf[cur][f * 4 + i], Ah[f][i], Al[f][i]);

            const uint4 Bh0 = Wf[cur][0], Bh1 = Wf[cur][1];
            const uint4 Bl0 = Wf[cur][2], Bl1 = Wf[cur][3];

            // pass hi*hi
#pragma unroll
            for (int f = 0; f < 2; ++f) {
                mma_tf32(acc[f][0], Ah[f][0], Ah[f][1], Ah[f][2], Ah[f][3], Bh0.x, Bh0.y);
                mma_tf32(acc[f][1], Ah[f][0], Ah[f][1], Ah[f][2], Ah[f][3], Bh0.z, Bh0.w);
                mma_tf32(acc[f][2], Ah[f][0], Ah[f][1], Ah[f][2], Ah[f][3], Bh1.x, Bh1.y);
                mma_tf32(acc[f][3], Ah[f][0], Ah[f][1], Ah[f][2], Ah[f][3], Bh1.z, Bh1.w);
            }
            // pass hi*lo
#pragma unroll
            for (int f = 0; f < 2; ++f) {
                mma_tf32(acc[f][0], Ah[f][0], Ah[f][1], Ah[f][2], Ah[f][3], Bl0.x, Bl0.y);
                mma_tf32(acc[f][1], Ah[f][0], Ah[f][1], Ah[f][2], Ah[f][3], Bl0.z, Bl0.w);
                mma_tf32(acc[f][2], Ah[f][0], Ah[f][1], Ah[f][2], Ah[f][3], Bl1.x, Bl1.y);
                mma_tf32(acc[f][3], Ah[f][0], Ah[f][1], Ah[f][2], Ah[f][3], Bl1.z, Bl1.w);
            }
            // pass lo*hi
#pragma unroll
            for (int f = 0; f < 2; ++f) {
                mma_tf32(acc[f][0], Al[f][0], Al[f][1], Al[f][2], Al[f][3], Bh0.x, Bh0.y);
                mma_tf32(acc[f][1], Al[f][0], Al[f][1], Al[f][2], Al[f][3], Bh0.z, Bh0.w);
                mma_tf32(acc[f][2], Al[f][0], Al[f][1], Al[f][2], Al[f][3], Bh1.x, Bh1.y);
                mma_tf32(acc[f][3], Al[f][0], Al[f][1], Al[f][2], Al[f][3], Bh1.z, Bh1.w);
            }
        }
        __syncthreads();
        stage = (stage + 1 == NSTAGE) ? 0 : stage + 1;
    }

    // ---- stage accumulators to smem ----
    float* Cs = reinterpret_cast<float*>(smem);
#pragma unroll
    for (int f = 0; f < 2; ++f)
#pragma unroll
        for (int g = 0; g < 4; ++g) {
            const int row = wm * 32 + f * 16 + gid;
            const int col = wn * 32 + g * 8 + 2 * tig;
            *reinterpret_cast<float2*>(&Cs[row * PADC + col]) =
                make_float2(acc[f][g][0], acc[f][g][1]);
            *reinterpret_cast<float2*>(&Cs[(row + 8) * PADC + col]) =
                make_float2(acc[f][g][2], acc[f][g][3]);
        }
    __syncthreads();

    // ---- epilogue: one thread per token ----
    if (tid < MT) {
        const int tok = m0 + tid;
        const float* crow = &Cs[tid * PADC];

        float v1 = -INFINITY, v2 = -INFINITY;
        int   i1 = -1, i2 = -1;
#pragma unroll 8
        for (int e = 0; e < 64; ++e) {
            const float lg = crow[e]      + __ldg(&br[e]);
            const float ns = crow[64 + e] + __ldg(&bn[e]);
            const float sp = fmaxf(ns, 0.0f) + log1pf(expf(-fabsf(ns)));
            const float nv = lg + __ldg(&eps[(size_t)tok * 64 + e]) * sp;
            if (nv > v1)      { v2 = v1; i2 = i1; v1 = nv; i1 = e; }
            else if (nv > v2) { v2 = nv; i2 = e; }
        }

        const float ed = expf(v2 - v1);
        const float s  = 1.0f + ed;
        const float p1 = 1.0f / s;
        const float p2 = ed / s;

        float* orow = out + (size_t)tok * 64;
#pragma unroll
        for (int e4 = 0; e4 < 64; e4 += 4) {
            float vv[4] = {0.0f, 0.0f, 0.0f, 0.0f};
            if (i1 >= e4 && i1 < e4 + 4) vv[i1 - e4] = p1;
            if (i2 >= e4 && i2 < e4 + 4) vv[i2 - e4] = p2;
            *reinterpret_cast<float4*>(orow + e4) =
                make_float4(vv[0], vv[1], vv[2], vv[3]);
        }

        const long long ibase = (long long)Ntok * 64;
        if (out_size >= ibase + (long long)Ntok * 2) {
            out[ibase + (long long)tok * 2 + 0] = (float)i1;
            out[ibase + (long long)tok * 2 + 1] = (float)i2;
        }
    }
}

extern "C" void kernel_launch(void* const* d_in, const int* in_sizes, int n_in,
                              void* d_out, int out_size)
{
    const float* x   = (const float*)d_in[0];
    const float* Wr  = (const float*)d_in[1];
    const float* br  = (const float*)d_in[2];
    const float* Wn  = (const float*)d_in[3];
    const float* bn  = (const float*)d_in[4];
    const float* eps = (const float*)d_in[5];
    float* out = (float*)d_out;
    (void)n_in;

    const int E    = in_sizes[2];              // 64
    const int D    = in_sizes[1] / E;          // 2048
    const int Ntok = in_sizes[0] / D;          // 32768

    static int configured = 0;                 // idempotent attribute set
    if (!configured) {
        cudaFuncSetAttribute(noisy_topk_router_mma,
                             cudaFuncAttributeMaxDynamicSharedMemorySize, SMEMB);
        configured = 1;
    }

    presplit_w<<<D / 32, 256>>>(Wr, Wn, D);
    noisy_topk_router_mma<<<Ntok / MT, THREADS, SMEMB>>>(
        x, br, bn, eps, out, Ntok, D, (long long)out_size);
}